// round 3
// baseline (speedup 1.0000x reference)
#include <cuda_runtime.h>
#include <cstdint>

// Problem constants (fixed by reference setup_inputs)
#define NN 50000
#define NE 1600000
#define KCH 128      // IN_CH
#define OC  128      // HEADS*OUT_CH
#define NHEADS 4
#define NEG_SLOPE 0.2f
#define EPSV 1e-9f

// ----- device scratch (static; no allocations allowed) -----
__device__ __align__(16) float g_h[(size_t)NN * OC];   // projected features [N,128]
__device__ __align__(16) float g_as[NN * NHEADS];      // per-node src logits
__device__ __align__(16) float g_ad[NN * NHEADS];      // per-node dst logits
__device__ __align__(16) float g_den[NN * NHEADS];     // softmax denominator (init = self exp)
__device__ __align__(16) float g_sa[NN * NHEADS];      // self exp -> self alpha
__device__ int g_ei[2 * NE];                           // int32 edge index (converted)
__device__ int g_is64;                                 // 1 if edge_index is int64

__device__ __forceinline__ float lrelu(float s) {
    return s >= 0.0f ? s : NEG_SLOPE * s;
}

// ============================================================
// K0: probe edge_index dtype (int32 vs int64), device-side.
// Reading int32 data as int64 combines pairs -> huge values.
// ============================================================
__global__ void k_detect(const void* ei) {
    const long long* e64 = (const long long*)ei;
    int ok = 1;
    for (int i = 0; i < 64; i++) {
        long long v = e64[i];
        if (v < 0 || v >= NN) ok = 0;
    }
    g_is64 = ok;
}

// ============================================================
// K0b: convert edge_index to int32 scratch (coalesced)
// ============================================================
__global__ void __launch_bounds__(256) k_convert(const void* __restrict__ ei) {
    int i = blockIdx.x * blockDim.x + threadIdx.x;
    if (i >= 2 * NE) return;
    int v;
    if (g_is64) v = (int)((const long long*)ei)[i];
    else        v = ((const int*)ei)[i];
    g_ei[i] = v;
}

// ============================================================
// K1: h = x @ W   (fp32 SGEMM, 128x128 block tile, 8x8 micro)
// ============================================================
__global__ void __launch_bounds__(256) k_gemm(const float* __restrict__ x,
                                              const float* __restrict__ W) {
    __shared__ float sX[128][33];   // [row][k-chunk], padded
    __shared__ float sW[32][128];   // [k][c]

    const int row0 = blockIdx.x * 128;
    const int tx = threadIdx.x & 15;   // col group
    const int ty = threadIdx.x >> 4;   // row group

    float acc[8][8];
#pragma unroll
    for (int i = 0; i < 8; i++)
#pragma unroll
        for (int j = 0; j < 8; j++) acc[i][j] = 0.0f;

    for (int kc = 0; kc < KCH; kc += 32) {
        __syncthreads();
        for (int i = threadIdx.x; i < 128 * 8; i += 256) {
            int r = i >> 3, q = i & 7;
            int gr = row0 + r;
            float4 v = make_float4(0.f, 0.f, 0.f, 0.f);
            if (gr < NN) v = *(const float4*)&x[(size_t)gr * KCH + kc + q * 4];
            sX[r][q * 4 + 0] = v.x; sX[r][q * 4 + 1] = v.y;
            sX[r][q * 4 + 2] = v.z; sX[r][q * 4 + 3] = v.w;
        }
        for (int i = threadIdx.x; i < 32 * 32; i += 256) {
            int k = i >> 5, q = i & 31;
            float4 v = *(const float4*)&W[(size_t)(kc + k) * OC + q * 4];
            *(float4*)&sW[k][q * 4] = v;
        }
        __syncthreads();

#pragma unroll 8
        for (int k = 0; k < 32; k++) {
            float xv[8], wv[8];
#pragma unroll
            for (int j = 0; j < 4; j++) {
                xv[j]     = sX[ty * 4 + j][k];
                xv[4 + j] = sX[ty * 4 + 64 + j][k];
            }
            float4 wa = *(float4*)&sW[k][tx * 4];
            float4 wb = *(float4*)&sW[k][tx * 4 + 64];
            wv[0] = wa.x; wv[1] = wa.y; wv[2] = wa.z; wv[3] = wa.w;
            wv[4] = wb.x; wv[5] = wb.y; wv[6] = wb.z; wv[7] = wb.w;
#pragma unroll
            for (int i = 0; i < 8; i++)
#pragma unroll
                for (int j = 0; j < 8; j++)
                    acc[i][j] = fmaf(xv[i], wv[j], acc[i][j]);
        }
    }

#pragma unroll
    for (int i = 0; i < 8; i++) {
        int r = row0 + ((i < 4) ? (ty * 4 + i) : (ty * 4 + 64 + i - 4));
        if (r < NN) {
            float4 va = make_float4(acc[i][0], acc[i][1], acc[i][2], acc[i][3]);
            float4 vb = make_float4(acc[i][4], acc[i][5], acc[i][6], acc[i][7]);
            *(float4*)&g_h[(size_t)r * OC + tx * 4]      = va;
            *(float4*)&g_h[(size_t)r * OC + tx * 4 + 64] = vb;
        }
    }
}

// ============================================================
// K2: per-node logits a_s/a_d; init denom with self-loop exp;
//     store self exp; zero d_out.    One warp per node.
// ============================================================
__global__ void __launch_bounds__(256) k_node_prep(const float* __restrict__ att_src,
                                                   const float* __restrict__ att_dst,
                                                   float* __restrict__ out) {
    int w = (blockIdx.x * blockDim.x + threadIdx.x) >> 5;
    int lane = threadIdx.x & 31;
    if (w >= NN) return;

    float4 hv = *(const float4*)&g_h[(size_t)w * OC + lane * 4];
    int head = lane >> 3;
    int cc = (lane & 7) * 4;
    float4 a4 = *(const float4*)&att_src[head * 32 + cc];
    float4 d4 = *(const float4*)&att_dst[head * 32 + cc];
    float s = hv.x * a4.x + hv.y * a4.y + hv.z * a4.z + hv.w * a4.w;
    float d = hv.x * d4.x + hv.y * d4.y + hv.z * d4.z + hv.w * d4.w;
#pragma unroll
    for (int o = 4; o >= 1; o >>= 1) {
        s += __shfl_xor_sync(0xFFFFFFFFu, s, o);
        d += __shfl_xor_sync(0xFFFFFFFFu, d, o);
    }
    if ((lane & 7) == 0) {
        g_as[w * NHEADS + head] = s;
        g_ad[w * NHEADS + head] = d;
    }
    // broadcast head sums to lanes 0..3 for the self-loop exp
    float sh = __shfl_sync(0xFFFFFFFFu, s, (lane & 3) * 8);
    float dh = __shfl_sync(0xFFFFFFFFu, d, (lane & 3) * 8);
    if (lane < 4) {
        float es = __expf(lrelu(sh + dh));
        g_den[w * NHEADS + lane] = es;   // self contribution seeds denominator
        g_sa[w * NHEADS + lane]  = es;   // numerator for self alpha
    }
    *(float4*)&out[(size_t)w * OC + lane * 4] = make_float4(0.f, 0.f, 0.f, 0.f);
}

// ============================================================
// K3: edge pass — denominator accumulation (vector red)
// ============================================================
__global__ void __launch_bounds__(256) k_edge_den(void) {
    int e = blockIdx.x * blockDim.x + threadIdx.x;
    if (e >= NE) return;
    int src = g_ei[e];
    int dst = g_ei[NE + e];
    float4 a = *(const float4*)&g_as[src * NHEADS];
    float4 b = *(const float4*)&g_ad[dst * NHEADS];
    float e0 = __expf(lrelu(a.x + b.x));
    float e1 = __expf(lrelu(a.y + b.y));
    float e2 = __expf(lrelu(a.z + b.z));
    float e3 = __expf(lrelu(a.w + b.w));
    asm volatile("red.global.add.v4.f32 [%0], {%1,%2,%3,%4};"
                 :: "l"(&g_den[dst * NHEADS]), "f"(e0), "f"(e1), "f"(e2), "f"(e3)
                 : "memory");
}

// ============================================================
// K4: per-(node,head) — finalize self alpha
// ============================================================
__global__ void __launch_bounds__(256) k_self(void) {
    int i = blockIdx.x * blockDim.x + threadIdx.x;
    if (i >= NN * NHEADS) return;
    g_sa[i] = g_sa[i] / (g_den[i] + EPSV);
}

// ============================================================
// K5: edge aggregation — one warp per edge, vector red scatter
// ============================================================
__global__ void __launch_bounds__(256) k_edge_agg(float* __restrict__ out) {
    int gw = (blockIdx.x * blockDim.x + threadIdx.x) >> 5;
    int lane = threadIdx.x & 31;
    if (gw >= NE) return;
    int src = g_ei[gw];
    int dst = g_ei[NE + gw];
    int head = lane >> 3;
    float s = lrelu(g_as[src * NHEADS + head] + g_ad[dst * NHEADS + head]);
    float alpha = __expf(s) / (g_den[dst * NHEADS + head] + EPSV);
    float4 hv = *(const float4*)&g_h[(size_t)src * OC + lane * 4];
    float vx = alpha * hv.x, vy = alpha * hv.y, vz = alpha * hv.z, vw = alpha * hv.w;
    asm volatile("red.global.add.v4.f32 [%0], {%1,%2,%3,%4};"
                 :: "l"(&out[(size_t)dst * OC + lane * 4]),
                    "f"(vx), "f"(vy), "f"(vz), "f"(vw)
                 : "memory");
}

// ============================================================
// K6: finalize — add self-loop message and bias
// ============================================================
__global__ void __launch_bounds__(256) k_final(float* __restrict__ out,
                                               const float* __restrict__ bias) {
    size_t i = (size_t)blockIdx.x * blockDim.x + threadIdx.x;
    if (i >= (size_t)NN * OC) return;
    int j = (int)(i & (OC - 1));
    int n = (int)(i >> 7);
    int head = j >> 5;
    out[i] = out[i] + g_sa[n * NHEADS + head] * g_h[i] + bias[j];
}

// ============================================================
extern "C" void kernel_launch(void* const* d_in, const int* in_sizes, int n_in,
                              void* d_out, int out_size) {
    const float* x       = (const float*)d_in[0];
    const void*  ei      = (const void*)d_in[1];
    const float* W       = (const float*)d_in[2];
    const float* att_src = (const float*)d_in[3];
    const float* att_dst = (const float*)d_in[4];
    const float* bias    = (const float*)d_in[5];
    float*       out     = (float*)d_out;

    k_detect<<<1, 1>>>(ei);
    k_convert<<<(2 * NE + 255) / 256, 256>>>(ei);
    k_gemm<<<(NN + 127) / 128, 256>>>(x, W);
    k_node_prep<<<(NN * 32 + 255) / 256, 256>>>(att_src, att_dst, out);
    k_edge_den<<<(NE + 255) / 256, 256>>>();
    k_self<<<(NN * NHEADS + 255) / 256, 256>>>();
    k_edge_agg<<<(NE * 32 + 255) / 256, 256>>>(out);
    k_final<<<(int)(((size_t)NN * OC + 255) / 256), 256>>>(out, bias);
}

// round 4
// speedup vs baseline: 1.2264x; 1.2264x over previous
#include <cuda_runtime.h>
#include <cstdint>

// Problem constants (fixed by reference setup_inputs)
#define NN 50000
#define NE 1600000
#define KCH 128      // IN_CH
#define OC  128      // HEADS*OUT_CH
#define NHEADS 4
#define NEG_SLOPE 0.2f
#define EPSV 1e-9f

// ----- device scratch (static; no allocations allowed) -----
__device__ __align__(16) float g_h[(size_t)NN * OC];   // projected features [N,128]
__device__ __align__(16) float g_as[NN * NHEADS];      // per-node src logits
__device__ __align__(16) float g_ad[NN * NHEADS];      // per-node dst logits
__device__ __align__(16) float g_self[NN * NHEADS];    // self-loop exp(lrelu(as+ad))
__device__ int g_ei[2 * NE];    // int32 edge index (converted)
__device__ int g_cnt[NN];       // in-degree histogram
__device__ int g_off[NN + 1];   // CSR offsets
__device__ int g_cur[NN];       // scatter cursors
__device__ int g_esrc[NE];      // CSR: src ids grouped by dst
__device__ int g_is64;          // 1 if edge_index is int64

__device__ __forceinline__ float lrelu(float s) {
    return s >= 0.0f ? s : NEG_SLOPE * s;
}

// ============================================================
// K0: probe edge_index dtype (int32 vs int64), device-side.
// ============================================================
__global__ void k_detect(const void* ei) {
    const long long* e64 = (const long long*)ei;
    int ok = 1;
#pragma unroll 8
    for (int i = 0; i < 64; i++) {
        long long v = e64[i];
        if (v < 0 || v >= NN) ok = 0;
    }
    g_is64 = ok;
}

// ============================================================
// K0a: zero the degree histogram (graph replays need re-zero)
// ============================================================
__global__ void __launch_bounds__(256) k_zero(void) {
    int i = blockIdx.x * blockDim.x + threadIdx.x;
    if (i < NN) g_cnt[i] = 0;
}

// ============================================================
// K0b: convert edge_index to int32 + build dst histogram
// ============================================================
__global__ void __launch_bounds__(256) k_convert_hist(const void* __restrict__ ei) {
    int i = blockIdx.x * blockDim.x + threadIdx.x;
    if (i >= 2 * NE) return;
    int v;
    if (g_is64) v = (int)((const long long*)ei)[i];
    else        v = ((const int*)ei)[i];
    g_ei[i] = v;
    if (i >= NE) atomicAdd(&g_cnt[v], 1);   // dst half
}

// ============================================================
// K1: h = x @ W   (fp32 SGEMM, 128x128 block tile, 8x8 micro)
// ============================================================
__global__ void __launch_bounds__(256) k_gemm(const float* __restrict__ x,
                                              const float* __restrict__ W) {
    __shared__ float sX[128][33];
    __shared__ float sW[32][128];

    const int row0 = blockIdx.x * 128;
    const int tx = threadIdx.x & 15;
    const int ty = threadIdx.x >> 4;

    float acc[8][8];
#pragma unroll
    for (int i = 0; i < 8; i++)
#pragma unroll
        for (int j = 0; j < 8; j++) acc[i][j] = 0.0f;

    for (int kc = 0; kc < KCH; kc += 32) {
        __syncthreads();
        for (int i = threadIdx.x; i < 128 * 8; i += 256) {
            int r = i >> 3, q = i & 7;
            int gr = row0 + r;
            float4 v = make_float4(0.f, 0.f, 0.f, 0.f);
            if (gr < NN) v = *(const float4*)&x[(size_t)gr * KCH + kc + q * 4];
            sX[r][q * 4 + 0] = v.x; sX[r][q * 4 + 1] = v.y;
            sX[r][q * 4 + 2] = v.z; sX[r][q * 4 + 3] = v.w;
        }
        for (int i = threadIdx.x; i < 32 * 32; i += 256) {
            int k = i >> 5, q = i & 31;
            float4 v = *(const float4*)&W[(size_t)(kc + k) * OC + q * 4];
            *(float4*)&sW[k][q * 4] = v;
        }
        __syncthreads();

#pragma unroll 8
        for (int k = 0; k < 32; k++) {
            float xv[8], wv[8];
#pragma unroll
            for (int j = 0; j < 4; j++) {
                xv[j]     = sX[ty * 4 + j][k];
                xv[4 + j] = sX[ty * 4 + 64 + j][k];
            }
            float4 wa = *(float4*)&sW[k][tx * 4];
            float4 wb = *(float4*)&sW[k][tx * 4 + 64];
            wv[0] = wa.x; wv[1] = wa.y; wv[2] = wa.z; wv[3] = wa.w;
            wv[4] = wb.x; wv[5] = wb.y; wv[6] = wb.z; wv[7] = wb.w;
#pragma unroll
            for (int i = 0; i < 8; i++)
#pragma unroll
                for (int j = 0; j < 8; j++)
                    acc[i][j] = fmaf(xv[i], wv[j], acc[i][j]);
        }
    }

#pragma unroll
    for (int i = 0; i < 8; i++) {
        int r = row0 + ((i < 4) ? (ty * 4 + i) : (ty * 4 + 64 + i - 4));
        if (r < NN) {
            float4 va = make_float4(acc[i][0], acc[i][1], acc[i][2], acc[i][3]);
            float4 vb = make_float4(acc[i][4], acc[i][5], acc[i][6], acc[i][7]);
            *(float4*)&g_h[(size_t)r * OC + tx * 4]      = va;
            *(float4*)&g_h[(size_t)r * OC + tx * 4 + 64] = vb;
        }
    }
}

// ============================================================
// K2: per-node logits a_s/a_d and self-loop exp. Warp per node.
// ============================================================
__global__ void __launch_bounds__(256) k_node_prep(const float* __restrict__ att_src,
                                                   const float* __restrict__ att_dst) {
    int w = (blockIdx.x * blockDim.x + threadIdx.x) >> 5;
    int lane = threadIdx.x & 31;
    if (w >= NN) return;

    float4 hv = *(const float4*)&g_h[(size_t)w * OC + lane * 4];
    int head = lane >> 3;
    int cc = (lane & 7) * 4;
    float4 a4 = *(const float4*)&att_src[head * 32 + cc];
    float4 d4 = *(const float4*)&att_dst[head * 32 + cc];
    float s = hv.x * a4.x + hv.y * a4.y + hv.z * a4.z + hv.w * a4.w;
    float d = hv.x * d4.x + hv.y * d4.y + hv.z * d4.z + hv.w * d4.w;
#pragma unroll
    for (int o = 4; o >= 1; o >>= 1) {
        s += __shfl_xor_sync(0xFFFFFFFFu, s, o);
        d += __shfl_xor_sync(0xFFFFFFFFu, d, o);
    }
    if ((lane & 7) == 0) {
        g_as[w * NHEADS + head] = s;
        g_ad[w * NHEADS + head] = d;
    }
    float sh = __shfl_sync(0xFFFFFFFFu, s, (lane & 3) * 8);
    float dh = __shfl_sync(0xFFFFFFFFu, d, (lane & 3) * 8);
    if (lane < 4) {
        g_self[w * NHEADS + lane] = __expf(lrelu(sh + dh));
    }
}

// ============================================================
// K3: exclusive prefix scan of g_cnt -> g_off, g_cur.
// Single block, 1024 threads, ~49 items each.
// ============================================================
#define SCAN_T 1024
#define SCAN_ITEMS ((NN + SCAN_T - 1) / SCAN_T)
__global__ void __launch_bounds__(SCAN_T) k_scan(void) {
    __shared__ int sh[SCAN_T];
    int t = threadIdx.x;
    int base = t * SCAN_ITEMS;
    int sum = 0;
    for (int i = 0; i < SCAN_ITEMS; i++) {
        int idx = base + i;
        if (idx < NN) sum += g_cnt[idx];
    }
    sh[t] = sum;
    __syncthreads();
    for (int o = 1; o < SCAN_T; o <<= 1) {
        int v = 0;
        if (t >= o) v = sh[t - o];
        __syncthreads();
        if (t >= o) sh[t] += v;
        __syncthreads();
    }
    int run = (t == 0) ? 0 : sh[t - 1];
    for (int i = 0; i < SCAN_ITEMS; i++) {
        int idx = base + i;
        if (idx < NN) {
            g_off[idx] = run;
            g_cur[idx] = run;
            run += g_cnt[idx];
        }
    }
    if (t == SCAN_T - 1) g_off[NN] = NE;
}

// ============================================================
// K4: scatter src ids into dst-grouped CSR (int atomics)
// ============================================================
__global__ void __launch_bounds__(256) k_scatter(void) {
    int e = blockIdx.x * blockDim.x + threadIdx.x;
    if (e >= NE) return;
    int src = g_ei[e];
    int dst = g_ei[NE + e];
    int pos = atomicAdd(&g_cur[dst], 1);
    g_esrc[pos] = src;
}

// ============================================================
// K5: fused softmax + aggregation, atomic-free.
// Warp per dst node; lanes cover 4 channels each.
// ============================================================
__global__ void __launch_bounds__(256) k_agg(float* __restrict__ out,
                                             const float* __restrict__ bias) {
    int w = (blockIdx.x * blockDim.x + threadIdx.x) >> 5;
    int lane = threadIdx.x & 31;
    if (w >= NN) return;
    int head = lane >> 3;
    int c4 = lane * 4;

    float adh = g_ad[w * NHEADS + head];
    float es  = g_self[w * NHEADS + head];
    float den = es;
    float4 hv = *(const float4*)&g_h[(size_t)w * OC + c4];
    float4 acc = make_float4(es * hv.x, es * hv.y, es * hv.z, es * hv.w);

    int beg = g_off[w], end = g_off[w + 1];
    for (int base = beg; base < end; base += 32) {
        int idx = base + lane;
        int sj = (idx < end) ? g_esrc[idx] : -1;
        int cnt = end - base; if (cnt > 32) cnt = 32;
#pragma unroll 8
        for (int j = 0; j < 32; j++) {
            if (j >= cnt) break;
            int src = __shfl_sync(0xFFFFFFFFu, sj, j);
            float e = __expf(lrelu(g_as[src * NHEADS + head] + adh));
            const float4 hs = *(const float4*)&g_h[(size_t)src * OC + c4];
            den += e;
            acc.x = fmaf(e, hs.x, acc.x);
            acc.y = fmaf(e, hs.y, acc.y);
            acc.z = fmaf(e, hs.z, acc.z);
            acc.w = fmaf(e, hs.w, acc.w);
        }
    }

    float inv = 1.0f / (den + EPSV);
    float4 b4 = *(const float4*)&bias[c4];
    float4 o4 = make_float4(acc.x * inv + b4.x, acc.y * inv + b4.y,
                            acc.z * inv + b4.z, acc.w * inv + b4.w);
    *(float4*)&out[(size_t)w * OC + c4] = o4;
}

// ============================================================
extern "C" void kernel_launch(void* const* d_in, const int* in_sizes, int n_in,
                              void* d_out, int out_size) {
    const float* x       = (const float*)d_in[0];
    const void*  ei      = (const void*)d_in[1];
    const float* W       = (const float*)d_in[2];
    const float* att_src = (const float*)d_in[3];
    const float* att_dst = (const float*)d_in[4];
    const float* bias    = (const float*)d_in[5];
    float*       out     = (float*)d_out;

    k_detect<<<1, 1>>>(ei);
    k_zero<<<(NN + 255) / 256, 256>>>();
    k_convert_hist<<<(2 * NE + 255) / 256, 256>>>(ei);
    k_gemm<<<(NN + 127) / 128, 256>>>(x, W);
    k_node_prep<<<(NN * 32 + 255) / 256, 256>>>(att_src, att_dst);
    k_scan<<<1, SCAN_T>>>();
    k_scatter<<<(NE + 255) / 256, 256>>>();
    k_agg<<<(NN * 32 + 255) / 256, 256>>>(out, bias);
}

// round 6
// speedup vs baseline: 1.6935x; 1.3809x over previous
#include <cuda_runtime.h>
#include <cuda_bf16.h>
#include <cstdint>

// Problem constants (fixed by reference setup_inputs)
#define NN 50000
#define NE 1600000
#define KCH 128      // IN_CH
#define OC  128      // HEADS*OUT_CH
#define NHEADS 4
#define NEG_SLOPE 0.2f
#define EPSV 1e-9f

#define NBLK 196                       // ceil(NN/256) scan blocks
#define GEMM_GRID ((NN + 127) / 128)   // 391

// ----- device scratch (static; no allocations allowed) -----
__device__ __align__(16) float g_h[(size_t)NN * OC];   // projected features [N,128]
__device__ __align__(16) float g_as[NN * NHEADS];      // per-node src logits
__device__ __align__(16) float g_ad[NN * NHEADS];      // per-node dst logits
__device__ __align__(16) float g_self[NN * NHEADS];    // self-loop exp
__device__ int g_ei[2 * NE];    // int32 edge index (converted)
__device__ int g_cnt[NN];       // in-degree histogram
__device__ int g_off[NN + 1];   // CSR offsets
__device__ int g_cur[NN];       // scatter cursors
__device__ int g_esrc[NE];      // CSR: src ids grouped by dst
__device__ int g_bsum[NBLK];    // scan block sums
__device__ int g_boff[NBLK];    // scan block offsets
__device__ int g_is64;          // 1 if edge_index is int64

__device__ __forceinline__ float lrelu(float s) {
    return s >= 0.0f ? s : NEG_SLOPE * s;
}

// ============================================================
// K0: detect dtype + zero histogram (fused)
// ============================================================
__global__ void __launch_bounds__(256) k_init(const void* ei) {
    int i = blockIdx.x * blockDim.x + threadIdx.x;
    if (i < NN) g_cnt[i] = 0;
    if (i == 0) {
        const long long* e64 = (const long long*)ei;
        int ok = 1;
        for (int j = 0; j < 64; j++) {
            long long v = e64[j];
            if (v < 0 || v >= NN) ok = 0;
        }
        g_is64 = ok;
    }
}

// ============================================================
// K1: convert edge_index to int32 + build dst histogram
// ============================================================
__global__ void __launch_bounds__(256) k_convert_hist(const void* __restrict__ ei) {
    int i = blockIdx.x * blockDim.x + threadIdx.x;
    if (i >= 2 * NE) return;
    int v;
    if (g_is64) v = (int)((const long long*)ei)[i];
    else        v = ((const int*)ei)[i];
    g_ei[i] = v;
    if (i >= NE) atomicAdd(&g_cnt[v], 1);
}

// ============================================================
// K2: h = x @ W via mma.sync bf16 2-term split (3 products)
// One CTA = 128x128 tile, 256 threads (8 warps 4Mx2N).
// ============================================================
#define SROW 136                      // bf16 row stride (conflict-free)
#define TILE_B (128 * SROW * 2)       // 34816 bytes per tile
#define SMA_HI 0
#define SMA_LO (TILE_B)
#define SMB_HI (2 * TILE_B)
#define SMB_LO (3 * TILE_B)
#define SM_TOTAL (4 * TILE_B)         // 139264 B dynamic smem

__device__ __forceinline__ void mma16816(float* d, const uint32_t* a, const uint32_t* b) {
    asm volatile(
        "mma.sync.aligned.m16n8k16.row.col.f32.bf16.bf16.f32 "
        "{%0,%1,%2,%3}, {%4,%5,%6,%7}, {%8,%9}, {%0,%1,%2,%3};"
        : "+f"(d[0]), "+f"(d[1]), "+f"(d[2]), "+f"(d[3])
        : "r"(a[0]), "r"(a[1]), "r"(a[2]), "r"(a[3]), "r"(b[0]), "r"(b[1]));
}

__global__ void __launch_bounds__(256) k_gemm_mma(const float* __restrict__ x,
                                                  const float* __restrict__ W) {
    extern __shared__ char smem[];
    __nv_bfloat16* sAh = (__nv_bfloat16*)(smem + SMA_HI);
    __nv_bfloat16* sAl = (__nv_bfloat16*)(smem + SMA_LO);
    __nv_bfloat16* sBh = (__nv_bfloat16*)(smem + SMB_HI);
    __nv_bfloat16* sBl = (__nv_bfloat16*)(smem + SMB_LO);

    const int tid = threadIdx.x;
    const int wid = tid >> 5;
    const int lane = tid & 31;
    const int row0 = blockIdx.x * 128;
    const int wm = wid & 3;        // M block of 32
    const int wn = wid >> 2;       // N block of 64

    // ---- convert A: x[row0+r][k] -> hi/lo bf16 ----
    for (int idx = tid; idx < 128 * 128; idx += 256) {
        int r = idx >> 7, k = idx & 127;
        int gr = row0 + r;
        float v = (gr < NN) ? x[(size_t)gr * KCH + k] : 0.0f;
        __nv_bfloat16 hi = __float2bfloat16_rn(v);
        __nv_bfloat16 lo = __float2bfloat16_rn(v - __bfloat162float(hi));
        sAh[r * SROW + k] = hi;
        sAl[r * SROW + k] = lo;
    }
    // ---- convert B (col-major for mma): sB[n][k] = W[k][n] ----
    for (int idx = tid; idx < 128 * 128; idx += 256) {
        int k = idx >> 7, n = idx & 127;     // coalesced W read
        float v = W[(size_t)k * OC + n];
        __nv_bfloat16 hi = __float2bfloat16_rn(v);
        __nv_bfloat16 lo = __float2bfloat16_rn(v - __bfloat162float(hi));
        sBh[n * SROW + k] = hi;
        sBl[n * SROW + k] = lo;
    }
    __syncthreads();

    float acc[2][8][4];
#pragma unroll
    for (int mf = 0; mf < 2; mf++)
#pragma unroll
        for (int nf = 0; nf < 8; nf++)
#pragma unroll
            for (int q = 0; q < 4; q++) acc[mf][nf][q] = 0.0f;

    const int ar = lane >> 2;           // fragment row/col-group
    const int ac = (lane & 3) * 2;      // k pair base

    for (int ks = 0; ks < 8; ks++) {
        const int k0 = ks * 16;
#pragma unroll
        for (int p = 0; p < 3; p++) {
            const __nv_bfloat16* A = (p == 2) ? sAl : sAh;   // hh, hl, lh
            const __nv_bfloat16* B = (p == 1) ? sBl : sBh;

            uint32_t bfr[8][2];
#pragma unroll
            for (int nf = 0; nf < 8; nf++) {
                int n = wn * 64 + nf * 8 + ar;
                const __nv_bfloat16* bp = &B[n * SROW + k0 + ac];
                bfr[nf][0] = *(const uint32_t*)bp;
                bfr[nf][1] = *(const uint32_t*)(bp + 8);
            }
#pragma unroll
            for (int mf = 0; mf < 2; mf++) {
                int r = wm * 32 + mf * 16 + ar;
                const __nv_bfloat16* ap = &A[r * SROW + k0 + ac];
                uint32_t afr[4];
                afr[0] = *(const uint32_t*)ap;
                afr[1] = *(const uint32_t*)(ap + 8 * SROW);
                afr[2] = *(const uint32_t*)(ap + 8);
                afr[3] = *(const uint32_t*)(ap + 8 * SROW + 8);
#pragma unroll
                for (int nf = 0; nf < 8; nf++)
                    mma16816(acc[mf][nf], afr, bfr[nf]);
            }
        }
    }

    // ---- epilogue: write fp32 accumulators to g_h ----
#pragma unroll
    for (int mf = 0; mf < 2; mf++) {
        int r_lo = row0 + wm * 32 + mf * 16 + ar;
        int r_hi = r_lo + 8;
#pragma unroll
        for (int nf = 0; nf < 8; nf++) {
            int c = wn * 64 + nf * 8 + ac;
            if (r_lo < NN)
                *(float2*)&g_h[(size_t)r_lo * OC + c] =
                    make_float2(acc[mf][nf][0], acc[mf][nf][1]);
            if (r_hi < NN)
                *(float2*)&g_h[(size_t)r_hi * OC + c] =
                    make_float2(acc[mf][nf][2], acc[mf][nf][3]);
        }
    }
}

// ============================================================
// K3: per-node logits a_s/a_d and self-loop exp. Warp per node.
// ============================================================
__global__ void __launch_bounds__(256) k_node_prep(const float* __restrict__ att_src,
                                                   const float* __restrict__ att_dst) {
    int w = (blockIdx.x * blockDim.x + threadIdx.x) >> 5;
    int lane = threadIdx.x & 31;
    if (w >= NN) return;

    float4 hv = *(const float4*)&g_h[(size_t)w * OC + lane * 4];
    int head = lane >> 3;
    int cc = (lane & 7) * 4;
    float4 a4 = *(const float4*)&att_src[head * 32 + cc];
    float4 d4 = *(const float4*)&att_dst[head * 32 + cc];
    float s = hv.x * a4.x + hv.y * a4.y + hv.z * a4.z + hv.w * a4.w;
    float d = hv.x * d4.x + hv.y * d4.y + hv.z * d4.z + hv.w * d4.w;
#pragma unroll
    for (int o = 4; o >= 1; o >>= 1) {
        s += __shfl_xor_sync(0xFFFFFFFFu, s, o);
        d += __shfl_xor_sync(0xFFFFFFFFu, d, o);
    }
    if ((lane & 7) == 0) {
        g_as[w * NHEADS + head] = s;
        g_ad[w * NHEADS + head] = d;
    }
    float sh = __shfl_sync(0xFFFFFFFFu, s, (lane & 3) * 8);
    float dh = __shfl_sync(0xFFFFFFFFu, d, (lane & 3) * 8);
    if (lane < 4) {
        g_self[w * NHEADS + lane] = __expf(lrelu(sh + dh));
    }
}

// ============================================================
// K4a/b/c: hierarchical exclusive scan of g_cnt -> g_off/g_cur
// ============================================================
__global__ void __launch_bounds__(256) k_scan1(void) {
    __shared__ int sh[256];
    int i = blockIdx.x * 256 + threadIdx.x;
    sh[threadIdx.x] = (i < NN) ? g_cnt[i] : 0;
    __syncthreads();
    for (int o = 128; o > 0; o >>= 1) {
        if (threadIdx.x < o) sh[threadIdx.x] += sh[threadIdx.x + o];
        __syncthreads();
    }
    if (threadIdx.x == 0) g_bsum[blockIdx.x] = sh[0];
}
__global__ void __launch_bounds__(256) k_scan2(void) {
    __shared__ int sh[256];
    int t = threadIdx.x;
    sh[t] = (t < NBLK) ? g_bsum[t] : 0;
    __syncthreads();
    for (int o = 1; o < 256; o <<= 1) {
        int v = (t >= o) ? sh[t - o] : 0;
        __syncthreads();
        sh[t] += v;
        __syncthreads();
    }
    if (t < NBLK) g_boff[t] = sh[t] - g_bsum[t];   // exclusive
}
__global__ void __launch_bounds__(256) k_scan3(void) {
    __shared__ int sh[256];
    int t = threadIdx.x;
    int i = blockIdx.x * 256 + t;
    int c = (i < NN) ? g_cnt[i] : 0;
    sh[t] = c;
    __syncthreads();
    for (int o = 1; o < 256; o <<= 1) {
        int v = (t >= o) ? sh[t - o] : 0;
        __syncthreads();
        sh[t] += v;
        __syncthreads();
    }
    if (i < NN) {
        int off = g_boff[blockIdx.x] + sh[t] - c;   // exclusive
        g_off[i] = off;
        g_cur[i] = off;
    }
    if (i == NN - 1) g_off[NN] = NE;
}

// ============================================================
// K5: scatter src ids into dst-grouped CSR (int atomics)
// ============================================================
__global__ void __launch_bounds__(256) k_scatter(void) {
    int e = blockIdx.x * blockDim.x + threadIdx.x;
    if (e >= NE) return;
    int src = g_ei[e];
    int dst = g_ei[NE + e];
    int pos = atomicAdd(&g_cur[dst], 1);
    g_esrc[pos] = src;
}

// ============================================================
// K6: fused softmax + aggregation, atomic-free. Warp per dst.
// ============================================================
__global__ void __launch_bounds__(256) k_agg(float* __restrict__ out,
                                             const float* __restrict__ bias) {
    int w = (blockIdx.x * blockDim.x + threadIdx.x) >> 5;
    int lane = threadIdx.x & 31;
    if (w >= NN) return;
    int head = lane >> 3;
    int c4 = lane * 4;

    float adh = g_ad[w * NHEADS + head];
    float es  = g_self[w * NHEADS + head];
    float den = es;
    float4 hv = *(const float4*)&g_h[(size_t)w * OC + c4];
    float4 acc = make_float4(es * hv.x, es * hv.y, es * hv.z, es * hv.w);

    int beg = g_off[w], end = g_off[w + 1];
    for (int base = beg; base < end; base += 32) {
        int idx = base + lane;
        int sj = (idx < end) ? g_esrc[idx] : -1;
        int cnt = end - base; if (cnt > 32) cnt = 32;
#pragma unroll 8
        for (int j = 0; j < 32; j++) {
            if (j >= cnt) break;
            int src = __shfl_sync(0xFFFFFFFFu, sj, j);
            float e = __expf(lrelu(g_as[src * NHEADS + head] + adh));
            const float4 hs = *(const float4*)&g_h[(size_t)src * OC + c4];
            den += e;
            acc.x = fmaf(e, hs.x, acc.x);
            acc.y = fmaf(e, hs.y, acc.y);
            acc.z = fmaf(e, hs.z, acc.z);
            acc.w = fmaf(e, hs.w, acc.w);
        }
    }

    float inv = 1.0f / (den + EPSV);
    float4 b4 = *(const float4*)&bias[c4];
    *(float4*)&out[(size_t)w * OC + c4] =
        make_float4(acc.x * inv + b4.x, acc.y * inv + b4.y,
                    acc.z * inv + b4.z, acc.w * inv + b4.w);
}

// ============================================================
extern "C" void kernel_launch(void* const* d_in, const int* in_sizes, int n_in,
                              void* d_out, int out_size) {
    const float* x       = (const float*)d_in[0];
    const void*  ei      = (const void*)d_in[1];
    const float* W       = (const float*)d_in[2];
    const float* att_src = (const float*)d_in[3];
    const float* att_dst = (const float*)d_in[4];
    const float* bias    = (const float*)d_in[5];
    float*       out     = (float*)d_out;

    static int smem_set = 0;
    if (!smem_set) {
        cudaFuncSetAttribute(k_gemm_mma,
                             cudaFuncAttributeMaxDynamicSharedMemorySize, SM_TOTAL);
        smem_set = 1;
    }

    k_init<<<(NN + 255) / 256, 256>>>(ei);
    k_convert_hist<<<(2 * NE + 255) / 256, 256>>>(ei);
    k_gemm_mma<<<GEMM_GRID, 256, SM_TOTAL>>>(x, W);
    k_node_prep<<<(NN * 32 + 255) / 256, 256>>>(att_src, att_dst);
    k_scan1<<<NBLK, 256>>>();
    k_scan2<<<1, 256>>>();
    k_scan3<<<NBLK, 256>>>();
    k_scatter<<<(NE + 255) / 256, 256>>>();
    k_agg<<<(NN * 32 + 255) / 256, 256>>>(out, bias);
}

// round 7
// speedup vs baseline: 1.8566x; 1.0963x over previous
#include <cuda_runtime.h>
#include <cuda_bf16.h>
#include <cstdint>

// Problem constants (fixed by reference setup_inputs)
#define NN 50000
#define NE 1600000
#define KCH 128      // IN_CH
#define OC  128      // HEADS*OUT_CH
#define NHEADS 4
#define NEG_SLOPE 0.2f
#define EPSV 1e-9f

#define NBLK 196                       // ceil(NN/256) scan blocks
#define GEMM_GRID ((NN + 127) / 128)   // 391

// ----- device scratch (static; no allocations allowed) -----
__device__ __align__(16) float g_h[(size_t)NN * OC];   // projected features [N,128]
__device__ __align__(16) float g_as[NN * NHEADS];      // per-node src logits
__device__ __align__(16) float g_ad[NN * NHEADS];      // per-node dst logits
__device__ __align__(16) float g_self[NN * NHEADS];    // self-loop exp
__device__ int g_cnt[NN];       // in-degree histogram
__device__ int g_off[NN + 1];   // CSR offsets
__device__ int g_cur[NN];       // scatter cursors
__device__ int g_esrc[NE];      // CSR: src ids grouped by dst
__device__ int g_bsum[NBLK];    // scan block sums
__device__ int g_boff[NBLK];    // scan block offsets
__device__ int g_is64;          // 1 if edge_index is int64

__device__ __forceinline__ float lrelu(float s) {
    return s >= 0.0f ? s : NEG_SLOPE * s;
}

// ============================================================
// K0: detect dtype + zero histogram (fused)
// ============================================================
__global__ void __launch_bounds__(256) k_init(const void* ei) {
    int i = blockIdx.x * blockDim.x + threadIdx.x;
    if (i < NN) g_cnt[i] = 0;
    if (i == 0) {
        const long long* e64 = (const long long*)ei;
        int ok = 1;
        for (int j = 0; j < 64; j++) {
            long long v = e64[j];
            if (v < 0 || v >= NN) ok = 0;
        }
        g_is64 = ok;
    }
}

// ============================================================
// K1: dst-degree histogram straight from input (2 edges/thread)
// ============================================================
__global__ void __launch_bounds__(256) k_hist(const void* __restrict__ ei) {
    int i = blockIdx.x * blockDim.x + threadIdx.x;
    if (i >= NE / 2) return;
    int d0, d1;
    if (g_is64) {
        longlong2 v = ((const longlong2*)((const long long*)ei + NE))[i];
        d0 = (int)v.x; d1 = (int)v.y;
    } else {
        int2 v = ((const int2*)((const int*)ei + NE))[i];
        d0 = v.x; d1 = v.y;
    }
    atomicAdd(&g_cnt[d0], 1);
    atomicAdd(&g_cnt[d1], 1);
}

// ============================================================
// K2: h = x @ W via mma.sync bf16 2-term split (3 products)
// + fused per-node logits a_s/a_d/self-exp epilogue.
// One CTA = 128x128 tile, 256 threads (8 warps 4Mx2N).
// ============================================================
#define SROW 136                      // bf16 row stride (conflict-free)
#define TILE_B (128 * SROW * 2)       // 34816 bytes per tile
#define SMA_HI 0
#define SMA_LO (TILE_B)
#define SMB_HI (2 * TILE_B)
#define SMB_LO (3 * TILE_B)
#define SM_RED (4 * TILE_B)           // reduction array: [128][4][2] floats
#define SM_TOTAL (SM_RED + 128 * 4 * 2 * 4)

__device__ __forceinline__ void mma16816(float* d, const uint32_t* a, const uint32_t* b) {
    asm volatile(
        "mma.sync.aligned.m16n8k16.row.col.f32.bf16.bf16.f32 "
        "{%0,%1,%2,%3}, {%4,%5,%6,%7}, {%8,%9}, {%0,%1,%2,%3};"
        : "+f"(d[0]), "+f"(d[1]), "+f"(d[2]), "+f"(d[3])
        : "r"(a[0]), "r"(a[1]), "r"(a[2]), "r"(a[3]), "r"(b[0]), "r"(b[1]));
}

__global__ void __launch_bounds__(256) k_gemm_mma(const float* __restrict__ x,
                                                  const float* __restrict__ W,
                                                  const float* __restrict__ att_src,
                                                  const float* __restrict__ att_dst) {
    extern __shared__ char smem[];
    __nv_bfloat16* sAh = (__nv_bfloat16*)(smem + SMA_HI);
    __nv_bfloat16* sAl = (__nv_bfloat16*)(smem + SMA_LO);
    __nv_bfloat16* sBh = (__nv_bfloat16*)(smem + SMB_HI);
    __nv_bfloat16* sBl = (__nv_bfloat16*)(smem + SMB_LO);
    float* sRed = (float*)(smem + SM_RED);   // [row][head][2] = s,d

    const int tid = threadIdx.x;
    const int wid = tid >> 5;
    const int lane = tid & 31;
    const int row0 = blockIdx.x * 128;
    const int wm = wid & 3;        // M block of 32
    const int wn = wid >> 2;       // N block of 64

    // ---- convert A: x[row0+r][k] -> hi/lo bf16 ----
    for (int idx = tid; idx < 128 * 128; idx += 256) {
        int r = idx >> 7, k = idx & 127;
        int gr = row0 + r;
        float v = (gr < NN) ? x[(size_t)gr * KCH + k] : 0.0f;
        __nv_bfloat16 hi = __float2bfloat16_rn(v);
        __nv_bfloat16 lo = __float2bfloat16_rn(v - __bfloat162float(hi));
        sAh[r * SROW + k] = hi;
        sAl[r * SROW + k] = lo;
    }
    // ---- convert B (col-major for mma): sB[n][k] = W[k][n] ----
    for (int idx = tid; idx < 128 * 128; idx += 256) {
        int k = idx >> 7, n = idx & 127;     // coalesced W read
        float v = W[(size_t)k * OC + n];
        __nv_bfloat16 hi = __float2bfloat16_rn(v);
        __nv_bfloat16 lo = __float2bfloat16_rn(v - __bfloat162float(hi));
        sBh[n * SROW + k] = hi;
        sBl[n * SROW + k] = lo;
    }
    __syncthreads();

    float acc[2][8][4];
#pragma unroll
    for (int mf = 0; mf < 2; mf++)
#pragma unroll
        for (int nf = 0; nf < 8; nf++)
#pragma unroll
            for (int q = 0; q < 4; q++) acc[mf][nf][q] = 0.0f;

    const int ar = lane >> 2;           // fragment row/col-group
    const int ac = (lane & 3) * 2;      // k pair base

    for (int ks = 0; ks < 8; ks++) {
        const int k0 = ks * 16;
#pragma unroll
        for (int p = 0; p < 3; p++) {
            const __nv_bfloat16* A = (p == 2) ? sAl : sAh;   // hh, hl, lh
            const __nv_bfloat16* B = (p == 1) ? sBl : sBh;

            uint32_t bfr[8][2];
#pragma unroll
            for (int nf = 0; nf < 8; nf++) {
                int n = wn * 64 + nf * 8 + ar;
                const __nv_bfloat16* bp = &B[n * SROW + k0 + ac];
                bfr[nf][0] = *(const uint32_t*)bp;
                bfr[nf][1] = *(const uint32_t*)(bp + 8);
            }
#pragma unroll
            for (int mf = 0; mf < 2; mf++) {
                int r = wm * 32 + mf * 16 + ar;
                const __nv_bfloat16* ap = &A[r * SROW + k0 + ac];
                uint32_t afr[4];
                afr[0] = *(const uint32_t*)ap;
                afr[1] = *(const uint32_t*)(ap + 8 * SROW);
                afr[2] = *(const uint32_t*)(ap + 8);
                afr[3] = *(const uint32_t*)(ap + 8 * SROW + 8);
#pragma unroll
                for (int nf = 0; nf < 8; nf++)
                    mma16816(acc[mf][nf], afr, bfr[nf]);
            }
        }
    }

    // ---- epilogue 1: write fp32 h to g_h ----
#pragma unroll
    for (int mf = 0; mf < 2; mf++) {
        int r_lo = row0 + wm * 32 + mf * 16 + ar;
        int r_hi = r_lo + 8;
#pragma unroll
        for (int nf = 0; nf < 8; nf++) {
            int c = wn * 64 + nf * 8 + ac;
            if (r_lo < NN)
                *(float2*)&g_h[(size_t)r_lo * OC + c] =
                    make_float2(acc[mf][nf][0], acc[mf][nf][1]);
            if (r_hi < NN)
                *(float2*)&g_h[(size_t)r_hi * OC + c] =
                    make_float2(acc[mf][nf][2], acc[mf][nf][3]);
        }
    }

    // ---- epilogue 2: fused a_s/a_d logits ----
    // thread's att coefficients: cols wn*64 + nf*8 + ac + q
    float aS[8][2], aD[8][2];
#pragma unroll
    for (int nf = 0; nf < 8; nf++) {
#pragma unroll
        for (int q = 0; q < 2; q++) {
            int col = wn * 64 + nf * 8 + ac + q;
            aS[nf][q] = att_src[col];
            aD[nf][q] = att_dst[col];
        }
    }
    // per (mf, rowhalf): partial dots split per local head (nf<4 vs nf>=4)
#pragma unroll
    for (int mf = 0; mf < 2; mf++) {
#pragma unroll
        for (int rp = 0; rp < 2; rp++) {
            float s0 = 0, s1 = 0, d0 = 0, d1 = 0;
#pragma unroll
            for (int nf = 0; nf < 8; nf++) {
                float v0 = acc[mf][nf][rp * 2 + 0];
                float v1 = acc[mf][nf][rp * 2 + 1];
                float ps = v0 * aS[nf][0] + v1 * aS[nf][1];
                float pd = v0 * aD[nf][0] + v1 * aD[nf][1];
                if (nf < 4) { s0 += ps; d0 += pd; }
                else        { s1 += ps; d1 += pd; }
            }
            // reduce over the 4 lanes of the quad (same ar, lane&3=0..3)
#pragma unroll
            for (int o = 1; o <= 2; o <<= 1) {
                s0 += __shfl_xor_sync(0xFFFFFFFFu, s0, o);
                s1 += __shfl_xor_sync(0xFFFFFFFFu, s1, o);
                d0 += __shfl_xor_sync(0xFFFFFFFFu, d0, o);
                d1 += __shfl_xor_sync(0xFFFFFFFFu, d1, o);
            }
            if ((lane & 3) == 0) {
                int row = wm * 32 + mf * 16 + rp * 8 + ar;
                int h0 = wn * 2;
                sRed[(row * 4 + h0) * 2 + 0] = s0;
                sRed[(row * 4 + h0) * 2 + 1] = d0;
                sRed[(row * 4 + h0 + 1) * 2 + 0] = s1;
                sRed[(row * 4 + h0 + 1) * 2 + 1] = d1;
            }
        }
    }
    __syncthreads();

    if (tid < 128) {
        int gr = row0 + tid;
        if (gr < NN) {
            float4 vs, vd, ve;
            float* p = &sRed[tid * 8];
            vs.x = p[0]; vd.x = p[1];
            vs.y = p[2]; vd.y = p[3];
            vs.z = p[4]; vd.z = p[5];
            vs.w = p[6]; vd.w = p[7];
            ve.x = __expf(lrelu(vs.x + vd.x));
            ve.y = __expf(lrelu(vs.y + vd.y));
            ve.z = __expf(lrelu(vs.z + vd.z));
            ve.w = __expf(lrelu(vs.w + vd.w));
            *(float4*)&g_as[gr * NHEADS] = vs;
            *(float4*)&g_ad[gr * NHEADS] = vd;
            *(float4*)&g_self[gr * NHEADS] = ve;
        }
    }
}

// ============================================================
// K3a/b/c: hierarchical exclusive scan of g_cnt -> g_off/g_cur
// ============================================================
__global__ void __launch_bounds__(256) k_scan1(void) {
    __shared__ int sh[256];
    int i = blockIdx.x * 256 + threadIdx.x;
    sh[threadIdx.x] = (i < NN) ? g_cnt[i] : 0;
    __syncthreads();
    for (int o = 128; o > 0; o >>= 1) {
        if (threadIdx.x < o) sh[threadIdx.x] += sh[threadIdx.x + o];
        __syncthreads();
    }
    if (threadIdx.x == 0) g_bsum[blockIdx.x] = sh[0];
}
__global__ void __launch_bounds__(256) k_scan2(void) {
    __shared__ int sh[256];
    int t = threadIdx.x;
    sh[t] = (t < NBLK) ? g_bsum[t] : 0;
    __syncthreads();
    for (int o = 1; o < 256; o <<= 1) {
        int v = (t >= o) ? sh[t - o] : 0;
        __syncthreads();
        sh[t] += v;
        __syncthreads();
    }
    if (t < NBLK) g_boff[t] = sh[t] - g_bsum[t];   // exclusive
}
__global__ void __launch_bounds__(256) k_scan3(void) {
    __shared__ int sh[256];
    int t = threadIdx.x;
    int i = blockIdx.x * 256 + t;
    int c = (i < NN) ? g_cnt[i] : 0;
    sh[t] = c;
    __syncthreads();
    for (int o = 1; o < 256; o <<= 1) {
        int v = (t >= o) ? sh[t - o] : 0;
        __syncthreads();
        sh[t] += v;
        __syncthreads();
    }
    if (i < NN) {
        int off = g_boff[blockIdx.x] + sh[t] - c;   // exclusive
        g_off[i] = off;
        g_cur[i] = off;
    }
    if (i == NN - 1) g_off[NN] = NE;
}

// ============================================================
// K4: scatter src ids into dst-grouped CSR (int atomics),
// reading src/dst straight from the input tensor.
// ============================================================
__global__ void __launch_bounds__(256) k_scatter(const void* __restrict__ ei) {
    int e = blockIdx.x * blockDim.x + threadIdx.x;
    if (e >= NE) return;
    int src, dst;
    if (g_is64) {
        src = (int)((const long long*)ei)[e];
        dst = (int)((const long long*)ei)[NE + e];
    } else {
        src = ((const int*)ei)[e];
        dst = ((const int*)ei)[NE + e];
    }
    int pos = atomicAdd(&g_cur[dst], 1);
    g_esrc[pos] = src;
}

// ============================================================
// K5: fused softmax + aggregation, atomic-free. Warp per dst.
// ============================================================
__global__ void __launch_bounds__(256) k_agg(float* __restrict__ out,
                                             const float* __restrict__ bias) {
    int w = (blockIdx.x * blockDim.x + threadIdx.x) >> 5;
    int lane = threadIdx.x & 31;
    if (w >= NN) return;
    int head = lane >> 3;
    int c4 = lane * 4;

    float adh = g_ad[w * NHEADS + head];
    float es  = g_self[w * NHEADS + head];
    float den = es;
    float4 hv = *(const float4*)&g_h[(size_t)w * OC + c4];
    float4 acc = make_float4(es * hv.x, es * hv.y, es * hv.z, es * hv.w);

    int beg = g_off[w], end = g_off[w + 1];
    for (int base = beg; base < end; base += 32) {
        int idx = base + lane;
        int sj = (idx < end) ? g_esrc[idx] : -1;
        int cnt = end - base; if (cnt > 32) cnt = 32;
#pragma unroll 8
        for (int j = 0; j < 32; j++) {
            if (j >= cnt) break;
            int src = __shfl_sync(0xFFFFFFFFu, sj, j);
            float e = __expf(lrelu(g_as[src * NHEADS + head] + adh));
            const float4 hs = *(const float4*)&g_h[(size_t)src * OC + c4];
            den += e;
            acc.x = fmaf(e, hs.x, acc.x);
            acc.y = fmaf(e, hs.y, acc.y);
            acc.z = fmaf(e, hs.z, acc.z);
            acc.w = fmaf(e, hs.w, acc.w);
        }
    }

    float inv = 1.0f / (den + EPSV);
    float4 b4 = *(const float4*)&bias[c4];
    *(float4*)&out[(size_t)w * OC + c4] =
        make_float4(acc.x * inv + b4.x, acc.y * inv + b4.y,
                    acc.z * inv + b4.z, acc.w * inv + b4.w);
}

// ============================================================
extern "C" void kernel_launch(void* const* d_in, const int* in_sizes, int n_in,
                              void* d_out, int out_size) {
    const float* x       = (const float*)d_in[0];
    const void*  ei      = (const void*)d_in[1];
    const float* W       = (const float*)d_in[2];
    const float* att_src = (const float*)d_in[3];
    const float* att_dst = (const float*)d_in[4];
    const float* bias    = (const float*)d_in[5];
    float*       out     = (float*)d_out;

    static int smem_set = 0;
    if (!smem_set) {
        cudaFuncSetAttribute(k_gemm_mma,
                             cudaFuncAttributeMaxDynamicSharedMemorySize, SM_TOTAL);
        smem_set = 1;
    }

    k_init<<<(NN + 255) / 256, 256>>>(ei);
    k_hist<<<(NE / 2 + 255) / 256, 256>>>(ei);
    k_gemm_mma<<<GEMM_GRID, 256, SM_TOTAL>>>(x, W, att_src, att_dst);
    k_scan1<<<NBLK, 256>>>();
    k_scan2<<<1, 256>>>();
    k_scan3<<<NBLK, 256>>>();
    k_scatter<<<(NE + 255) / 256, 256>>>(ei);
    k_agg<<<(NN * 32 + 255) / 256, 256>>>(out, bias);
}

// round 8
// speedup vs baseline: 2.1193x; 1.1415x over previous
#include <cuda_runtime.h>
#include <cuda_bf16.h>
#include <cstdint>

// Problem constants (fixed by reference setup_inputs)
#define NN 50000
#define NE 1600000
#define KCH 128      // IN_CH
#define OC  128      // HEADS*OUT_CH
#define NHEADS 4
#define NEG_SLOPE 0.2f
#define EPSV 1e-9f

#define NBLK 196                       // ceil(NN/256) scan blocks
#define GEMM_GRID ((NN + 127) / 128)   // 391

// ----- device scratch (static; no allocations allowed) -----
__device__ __align__(16) float g_h[(size_t)NN * OC];   // projected features [N,128]
__device__ __align__(16) float g_as[NN * NHEADS];      // per-node src logits
__device__ __align__(16) float g_ad[NN * NHEADS];      // per-node dst logits
__device__ __align__(16) float g_self[NN * NHEADS];    // self-loop exp
__device__ int g_cnt[NN];       // in-degree histogram (zeroed by k_scatter for next replay)
__device__ int g_off[NN + 1];   // CSR offsets
__device__ int g_cur[NN];       // scatter cursors
__device__ int g_esrc[NE];      // CSR: src ids grouped by dst
__device__ int g_bsum[NBLK];    // scan block sums
__device__ int g_boff[NBLK];    // scan block offsets
__device__ int g_is64;          // 1 if edge_index is int64

__device__ __forceinline__ float lrelu(float s) {
    return s >= 0.0f ? s : NEG_SLOPE * s;
}

// ============================================================
// K0: detect dtype (1 block)
// ============================================================
__global__ void k_detect(const void* ei) {
    if (threadIdx.x == 0) {
        const long long* e64 = (const long long*)ei;
        int ok = 1;
        for (int j = 0; j < 64; j++) {
            long long v = e64[j];
            if (v < 0 || v >= NN) ok = 0;
        }
        g_is64 = ok;
    }
}

// ============================================================
// K1: dst-degree histogram straight from input (2 edges/thread)
// ============================================================
__global__ void __launch_bounds__(256) k_hist(const void* __restrict__ ei) {
    int i = blockIdx.x * blockDim.x + threadIdx.x;
    if (i >= NE / 2) return;
    int d0, d1;
    if (g_is64) {
        longlong2 v = ((const longlong2*)((const long long*)ei + NE))[i];
        d0 = (int)v.x; d1 = (int)v.y;
    } else {
        int2 v = ((const int2*)((const int*)ei + NE))[i];
        d0 = v.x; d1 = v.y;
    }
    atomicAdd(&g_cnt[d0], 1);
    atomicAdd(&g_cnt[d1], 1);
}

// ============================================================
// K2: h = x @ W via mma.sync bf16 2-term split (3 products)
// + fused per-node logits a_s/a_d/self-exp epilogue.
// ============================================================
#define SROW 136                      // bf16 row stride (conflict-free)
#define TILE_B (128 * SROW * 2)       // 34816 bytes per tile
#define SMA_HI 0
#define SMA_LO (TILE_B)
#define SMB_HI (2 * TILE_B)
#define SMB_LO (3 * TILE_B)
#define SM_RED (4 * TILE_B)           // reduction array: [128][4][2] floats
#define SM_TOTAL (SM_RED + 128 * 4 * 2 * 4)

__device__ __forceinline__ void mma16816(float* d, const uint32_t* a, const uint32_t* b) {
    asm volatile(
        "mma.sync.aligned.m16n8k16.row.col.f32.bf16.bf16.f32 "
        "{%0,%1,%2,%3}, {%4,%5,%6,%7}, {%8,%9}, {%0,%1,%2,%3};"
        : "+f"(d[0]), "+f"(d[1]), "+f"(d[2]), "+f"(d[3])
        : "r"(a[0]), "r"(a[1]), "r"(a[2]), "r"(a[3]), "r"(b[0]), "r"(b[1]));
}

__global__ void __launch_bounds__(256) k_gemm_mma(const float* __restrict__ x,
                                                  const float* __restrict__ W,
                                                  const float* __restrict__ att_src,
                                                  const float* __restrict__ att_dst) {
    extern __shared__ char smem[];
    __nv_bfloat16* sAh = (__nv_bfloat16*)(smem + SMA_HI);
    __nv_bfloat16* sAl = (__nv_bfloat16*)(smem + SMA_LO);
    __nv_bfloat16* sBh = (__nv_bfloat16*)(smem + SMB_HI);
    __nv_bfloat16* sBl = (__nv_bfloat16*)(smem + SMB_LO);
    float* sRed = (float*)(smem + SM_RED);   // [row][head][2] = s,d

    const int tid = threadIdx.x;
    const int wid = tid >> 5;
    const int lane = tid & 31;
    const int row0 = blockIdx.x * 128;
    const int wm = wid & 3;        // M block of 32
    const int wn = wid >> 2;       // N block of 64

    for (int idx = tid; idx < 128 * 128; idx += 256) {
        int r = idx >> 7, k = idx & 127;
        int gr = row0 + r;
        float v = (gr < NN) ? x[(size_t)gr * KCH + k] : 0.0f;
        __nv_bfloat16 hi = __float2bfloat16_rn(v);
        __nv_bfloat16 lo = __float2bfloat16_rn(v - __bfloat162float(hi));
        sAh[r * SROW + k] = hi;
        sAl[r * SROW + k] = lo;
    }
    for (int idx = tid; idx < 128 * 128; idx += 256) {
        int k = idx >> 7, n = idx & 127;     // coalesced W read
        float v = W[(size_t)k * OC + n];
        __nv_bfloat16 hi = __float2bfloat16_rn(v);
        __nv_bfloat16 lo = __float2bfloat16_rn(v - __bfloat162float(hi));
        sBh[n * SROW + k] = hi;
        sBl[n * SROW + k] = lo;
    }
    __syncthreads();

    float acc[2][8][4];
#pragma unroll
    for (int mf = 0; mf < 2; mf++)
#pragma unroll
        for (int nf = 0; nf < 8; nf++)
#pragma unroll
            for (int q = 0; q < 4; q++) acc[mf][nf][q] = 0.0f;

    const int ar = lane >> 2;
    const int ac = (lane & 3) * 2;

    for (int ks = 0; ks < 8; ks++) {
        const int k0 = ks * 16;
#pragma unroll
        for (int p = 0; p < 3; p++) {
            const __nv_bfloat16* A = (p == 2) ? sAl : sAh;   // hh, hl, lh
            const __nv_bfloat16* B = (p == 1) ? sBl : sBh;

            uint32_t bfr[8][2];
#pragma unroll
            for (int nf = 0; nf < 8; nf++) {
                int n = wn * 64 + nf * 8 + ar;
                const __nv_bfloat16* bp = &B[n * SROW + k0 + ac];
                bfr[nf][0] = *(const uint32_t*)bp;
                bfr[nf][1] = *(const uint32_t*)(bp + 8);
            }
#pragma unroll
            for (int mf = 0; mf < 2; mf++) {
                int r = wm * 32 + mf * 16 + ar;
                const __nv_bfloat16* ap = &A[r * SROW + k0 + ac];
                uint32_t afr[4];
                afr[0] = *(const uint32_t*)ap;
                afr[1] = *(const uint32_t*)(ap + 8 * SROW);
                afr[2] = *(const uint32_t*)(ap + 8);
                afr[3] = *(const uint32_t*)(ap + 8 * SROW + 8);
#pragma unroll
                for (int nf = 0; nf < 8; nf++)
                    mma16816(acc[mf][nf], afr, bfr[nf]);
            }
        }
    }

    // ---- epilogue 1: write fp32 h to g_h ----
#pragma unroll
    for (int mf = 0; mf < 2; mf++) {
        int r_lo = row0 + wm * 32 + mf * 16 + ar;
        int r_hi = r_lo + 8;
#pragma unroll
        for (int nf = 0; nf < 8; nf++) {
            int c = wn * 64 + nf * 8 + ac;
            if (r_lo < NN)
                *(float2*)&g_h[(size_t)r_lo * OC + c] =
                    make_float2(acc[mf][nf][0], acc[mf][nf][1]);
            if (r_hi < NN)
                *(float2*)&g_h[(size_t)r_hi * OC + c] =
                    make_float2(acc[mf][nf][2], acc[mf][nf][3]);
        }
    }

    // ---- epilogue 2: fused a_s/a_d logits ----
    float aS[8][2], aD[8][2];
#pragma unroll
    for (int nf = 0; nf < 8; nf++) {
#pragma unroll
        for (int q = 0; q < 2; q++) {
            int col = wn * 64 + nf * 8 + ac + q;
            aS[nf][q] = att_src[col];
            aD[nf][q] = att_dst[col];
        }
    }
#pragma unroll
    for (int mf = 0; mf < 2; mf++) {
#pragma unroll
        for (int rp = 0; rp < 2; rp++) {
            float s0 = 0, s1 = 0, d0 = 0, d1 = 0;
#pragma unroll
            for (int nf = 0; nf < 8; nf++) {
                float v0 = acc[mf][nf][rp * 2 + 0];
                float v1 = acc[mf][nf][rp * 2 + 1];
                float ps = v0 * aS[nf][0] + v1 * aS[nf][1];
                float pd = v0 * aD[nf][0] + v1 * aD[nf][1];
                if (nf < 4) { s0 += ps; d0 += pd; }
                else        { s1 += ps; d1 += pd; }
            }
#pragma unroll
            for (int o = 1; o <= 2; o <<= 1) {
                s0 += __shfl_xor_sync(0xFFFFFFFFu, s0, o);
                s1 += __shfl_xor_sync(0xFFFFFFFFu, s1, o);
                d0 += __shfl_xor_sync(0xFFFFFFFFu, d0, o);
                d1 += __shfl_xor_sync(0xFFFFFFFFu, d1, o);
            }
            if ((lane & 3) == 0) {
                int row = wm * 32 + mf * 16 + rp * 8 + ar;
                int h0 = wn * 2;
                sRed[(row * 4 + h0) * 2 + 0] = s0;
                sRed[(row * 4 + h0) * 2 + 1] = d0;
                sRed[(row * 4 + h0 + 1) * 2 + 0] = s1;
                sRed[(row * 4 + h0 + 1) * 2 + 1] = d1;
            }
        }
    }
    __syncthreads();

    if (tid < 128) {
        int gr = row0 + tid;
        if (gr < NN) {
            float4 vs, vd, ve;
            float* p = &sRed[tid * 8];
            vs.x = p[0]; vd.x = p[1];
            vs.y = p[2]; vd.y = p[3];
            vs.z = p[4]; vd.z = p[5];
            vs.w = p[6]; vd.w = p[7];
            ve.x = __expf(lrelu(vs.x + vd.x));
            ve.y = __expf(lrelu(vs.y + vd.y));
            ve.z = __expf(lrelu(vs.z + vd.z));
            ve.w = __expf(lrelu(vs.w + vd.w));
            *(float4*)&g_as[gr * NHEADS] = vs;
            *(float4*)&g_ad[gr * NHEADS] = vd;
            *(float4*)&g_self[gr * NHEADS] = ve;
        }
    }
}

// ============================================================
// K3a/b/c: hierarchical exclusive scan of g_cnt -> g_off/g_cur
// ============================================================
__global__ void __launch_bounds__(256) k_scan1(void) {
    __shared__ int sh[256];
    int i = blockIdx.x * 256 + threadIdx.x;
    sh[threadIdx.x] = (i < NN) ? g_cnt[i] : 0;
    __syncthreads();
    for (int o = 128; o > 0; o >>= 1) {
        if (threadIdx.x < o) sh[threadIdx.x] += sh[threadIdx.x + o];
        __syncthreads();
    }
    if (threadIdx.x == 0) g_bsum[blockIdx.x] = sh[0];
}
__global__ void __launch_bounds__(256) k_scan2(void) {
    __shared__ int sh[256];
    int t = threadIdx.x;
    sh[t] = (t < NBLK) ? g_bsum[t] : 0;
    __syncthreads();
    for (int o = 1; o < 256; o <<= 1) {
        int v = (t >= o) ? sh[t - o] : 0;
        __syncthreads();
        sh[t] += v;
        __syncthreads();
    }
    if (t < NBLK) g_boff[t] = sh[t] - g_bsum[t];   // exclusive
}
__global__ void __launch_bounds__(256) k_scan3(void) {
    __shared__ int sh[256];
    int t = threadIdx.x;
    int i = blockIdx.x * 256 + t;
    int c = (i < NN) ? g_cnt[i] : 0;
    sh[t] = c;
    __syncthreads();
    for (int o = 1; o < 256; o <<= 1) {
        int v = (t >= o) ? sh[t - o] : 0;
        __syncthreads();
        sh[t] += v;
        __syncthreads();
    }
    if (i < NN) {
        int off = g_boff[blockIdx.x] + sh[t] - c;   // exclusive
        g_off[i] = off;
        g_cur[i] = off;
    }
    if (i == NN - 1) g_off[NN] = NE;
}

// ============================================================
// K4: scatter src ids into dst-grouped CSR (2 edges/thread) +
// re-zero g_cnt for the next graph replay (g_cnt is dead here).
// ============================================================
__global__ void __launch_bounds__(256) k_scatter(const void* __restrict__ ei) {
    int i = blockIdx.x * blockDim.x + threadIdx.x;
    if (i < NN) g_cnt[i] = 0;
    if (i >= NE / 2) return;
    int s0, s1, d0, d1;
    if (g_is64) {
        longlong2 vs = ((const longlong2*)((const long long*)ei))[i];
        longlong2 vd = ((const longlong2*)((const long long*)ei + NE))[i];
        s0 = (int)vs.x; s1 = (int)vs.y; d0 = (int)vd.x; d1 = (int)vd.y;
    } else {
        int2 vs = ((const int2*)((const int*)ei))[i];
        int2 vd = ((const int2*)((const int*)ei + NE))[i];
        s0 = vs.x; s1 = vs.y; d0 = vd.x; d1 = vd.y;
    }
    g_esrc[atomicAdd(&g_cur[d0], 1)] = s0;
    g_esrc[atomicAdd(&g_cur[d1], 1)] = s1;
}

// ============================================================
// K5: fused softmax + aggregation, atomic-free. Warp per dst.
// Full-block / remainder split for load batching (MLP).
// ============================================================
__global__ void __launch_bounds__(256) k_agg(float* __restrict__ out,
                                             const float* __restrict__ bias) {
    int w = (blockIdx.x * blockDim.x + threadIdx.x) >> 5;
    int lane = threadIdx.x & 31;
    if (w >= NN) return;
    int head = lane >> 3;
    int c4 = lane * 4;

    float adh = g_ad[w * NHEADS + head];
    float es  = g_self[w * NHEADS + head];
    float den = es;
    float4 hv = *(const float4*)&g_h[(size_t)w * OC + c4];
    float4 acc = make_float4(es * hv.x, es * hv.y, es * hv.z, es * hv.w);

    int base = g_off[w];
    const int end = g_off[w + 1];

    // full 32-edge blocks: fixed trip count, no early exit
    for (; base + 32 <= end; base += 32) {
        int sj = g_esrc[base + lane];
#pragma unroll 8
        for (int j = 0; j < 32; j++) {
            int src = __shfl_sync(0xFFFFFFFFu, sj, j);
            float e = __expf(lrelu(g_as[src * NHEADS + head] + adh));
            const float4 hs = *(const float4*)&g_h[(size_t)src * OC + c4];
            den += e;
            acc.x = fmaf(e, hs.x, acc.x);
            acc.y = fmaf(e, hs.y, acc.y);
            acc.z = fmaf(e, hs.z, acc.z);
            acc.w = fmaf(e, hs.w, acc.w);
        }
    }
    // remainder
    int rem = end - base;
    if (rem > 0) {
        int sj = (lane < rem) ? g_esrc[base + lane] : 0;
        for (int j = 0; j < rem; j++) {
            int src = __shfl_sync(0xFFFFFFFFu, sj, j);
            float e = __expf(lrelu(g_as[src * NHEADS + head] + adh));
            const float4 hs = *(const float4*)&g_h[(size_t)src * OC + c4];
            den += e;
            acc.x = fmaf(e, hs.x, acc.x);
            acc.y = fmaf(e, hs.y, acc.y);
            acc.z = fmaf(e, hs.z, acc.z);
            acc.w = fmaf(e, hs.w, acc.w);
        }
    }

    float inv = 1.0f / (den + EPSV);
    float4 b4 = *(const float4*)&bias[c4];
    *(float4*)&out[(size_t)w * OC + c4] =
        make_float4(acc.x * inv + b4.x, acc.y * inv + b4.y,
                    acc.z * inv + b4.z, acc.w * inv + b4.w);
}

// ============================================================
extern "C" void kernel_launch(void* const* d_in, const int* in_sizes, int n_in,
                              void* d_out, int out_size) {
    const float* x       = (const float*)d_in[0];
    const void*  ei      = (const void*)d_in[1];
    const float* W       = (const float*)d_in[2];
    const float* att_src = (const float*)d_in[3];
    const float* att_dst = (const float*)d_in[4];
    const float* bias    = (const float*)d_in[5];
    float*       out     = (float*)d_out;

    static cudaStream_t s2 = nullptr;
    static cudaEvent_t evFork = nullptr, evJoin = nullptr;
    if (!s2) {
        cudaFuncSetAttribute(k_gemm_mma,
                             cudaFuncAttributeMaxDynamicSharedMemorySize, SM_TOTAL);
        cudaStreamCreateWithFlags(&s2, cudaStreamNonBlocking);
        cudaEventCreateWithFlags(&evFork, cudaEventDisableTiming);
        cudaEventCreateWithFlags(&evJoin, cudaEventDisableTiming);
    }

    // fork: GEMM (independent of edge index) on s2
    cudaEventRecord(evFork, 0);
    cudaStreamWaitEvent(s2, evFork, 0);
    k_gemm_mma<<<GEMM_GRID, 256, SM_TOTAL, s2>>>(x, W, att_src, att_dst);
    cudaEventRecord(evJoin, s2);

    // main stream: CSR build chain
    k_detect<<<1, 32>>>(ei);
    k_hist<<<(NE / 2 + 255) / 256, 256>>>(ei);
    k_scan1<<<NBLK, 256>>>();
    k_scan2<<<1, 256>>>();
    k_scan3<<<NBLK, 256>>>();
    k_scatter<<<(NE / 2 + 255) / 256, 256>>>(ei);

    // join: agg needs both chains
    cudaStreamWaitEvent(0, evJoin, 0);
    k_agg<<<(NN * 32 + 255) / 256, 256>>>(out, bias);
}